// round 8
// baseline (speedup 1.0000x reference)
#include <cuda_runtime.h>
#include <math.h>

// Problem constants
#define BB 64
#define SS 512
#define PD 300       // feature dim
#define KK 50        // labels
#define KP 64        // padded labels
#define RR 5
#define NROWS (BB*SS)        // 32768
#define BM 32                // rows per K1 block
#define XSS 304              // xs smem row stride (mult of 4 -> 16B-aligned cp.async rows)
#define CH_ELEMS (150*KP*2)  // 19200 pair-packed chat floats
#define NCH 32               // k3 pooling chunks per batch (16 s each)

// Scratch (device globals; no runtime allocation allowed)
__device__ __align__(16) float g_chat2[CH_ELEMS];    // [pp=150][half=2][tx=16][q=4]
__device__ __align__(16) float g_G[NROWS*KK];        // [row][k] cosine scores
__device__ __align__(16) float g_beta[NROWS];        // softmax weights
__device__ __align__(16) float g_part[BB*NCH*PD];    // pooling partials

// ---- packed fp32x2 FMA (Blackwell FFMA2 path) ----
__device__ __forceinline__ void fma2(unsigned long long& d,
                                     unsigned long long a,
                                     unsigned long long b) {
    asm("fma.rn.f32x2 %0, %1, %2, %0;" : "+l"(d) : "l"(a), "l"(b));
}
__device__ __forceinline__ float sum2(unsigned long long v) {
    return __uint_as_float((unsigned)v) + __uint_as_float((unsigned)(v >> 32));
}
__device__ __forceinline__ unsigned s2u(const void* p) {
    unsigned a;
    asm("{ .reg .u64 t; cvta.to.shared.u64 t, %1; cvt.u32.u64 %0, t; }"
        : "=r"(a) : "l"(p));
    return a;
}
union F4U2 { float4 f; unsigned long long u[2]; };

// ============================================================
// K0: normalize label embeddings C -> packed g_chat2.
// Per pp (512B row): half=0 holds k pairs {4tx, 4tx+1}, half=1 {4tx+2, 4tx+3},
// each tx owning a contiguous 16B chunk -> one LDG.128 per half in k1.
// grid=4 blocks; norms computed redundantly per block (cheap, deterministic).
// ============================================================
__global__ void k0_chat(const float* __restrict__ C) {
    __shared__ float inv[KP];
    int tid = threadIdx.x;   // 256
    if (tid < KP) {
        float s = 0.f;
        if (tid < KK) {
            const float* row = C + tid * PD;
            for (int p = 0; p < PD; p++) s = fmaf(row[p], row[p], s);
            inv[tid] = 1.f / (sqrtf(s) + 0.001f);
        } else {
            inv[tid] = 0.f;
        }
    }
    __syncthreads();
    const int span = CH_ELEMS / 4;   // per block
    const int base = blockIdx.x * span;
    for (int ii = tid; ii < span; ii += 256) {
        int i    = base + ii;
        int pp   = i >> 7;
        int rem  = i & 127;
        int half = rem >> 6;
        int w    = rem & 63;
        int tx   = w >> 2;
        int q    = w & 3;
        int k    = 4 * tx + 2 * half + (q >> 1);
        int e    = q & 1;
        int p    = 2 * pp + e;
        float v = 0.f;
        if (k < KK) v = C[k * PD + p] * inv[k];
        g_chat2[i] = v;
    }
}

// ============================================================
// K1: gathered cosine-score GEMM, v3.
// Block: 32 rows x 64 k, 128 threads, 4x4 tile/thread.
// smem 39KB -> 5 blocks/SM (20 warps) for latency hiding.
// Loop processes 2 p-pairs: 4x LDS.128 (A) + 4x LDG.128 (B, L1-hot)
// issued up front, then 32 fma2.
// ============================================================
__global__ void __launch_bounds__(128, 5)
k1_scores(const int* __restrict__ idx, const float* __restrict__ emb) {
    extern __shared__ float xs[];    // BM * XSS
    __shared__ float inv[BM];

    const int tid  = threadIdx.x;
    const int lane = tid & 31;
    const int warp = tid >> 5;       // 0..3
    const int row0 = blockIdx.x * BM;

    // gather x rows via cp.async (8 rows per warp, all batched)
    for (int r = warp; r < BM; r += 4) {
        const float4* src = (const float4*)(emb + (size_t)idx[row0 + r] * PD);
        unsigned dst = s2u(xs + r * XSS);
        #pragma unroll
        for (int i = 0; i < 3; i++) {
            int p4 = lane + 32 * i;
            if (p4 < 75)
                asm volatile("cp.async.cg.shared.global [%0], [%1], 16;"
                             :: "r"(dst + 16u * (unsigned)p4), "l"(src + p4));
        }
    }
    asm volatile("cp.async.commit_group;");
    asm volatile("cp.async.wait_group 0;" ::: "memory");
    __syncthreads();

    // inverse norms (warp per row)
    for (int r = warp; r < BM; r += 4) {
        const float* xr = xs + r * XSS;
        float ss = 0.f;
        #pragma unroll
        for (int i = 0; i < 10; i++) {
            int p = lane + 32 * i;
            if (p < PD) { float v = xr[p]; ss = fmaf(v, v, ss); }
        }
        #pragma unroll
        for (int o = 16; o; o >>= 1) ss += __shfl_xor_sync(0xffffffffu, ss, o);
        if (lane == 0) inv[r] = 1.f / (sqrtf(ss) + 0.001f);
    }
    __syncthreads();

    const int tx = tid & 15;   // k direction (4 k each)
    const int ty = tid >> 4;   // 0..7 (4 rows each)

    unsigned long long acc[4][4];
    #pragma unroll
    for (int i = 0; i < 4; i++)
        #pragma unroll
        for (int j = 0; j < 4; j++) acc[i][j] = 0ull;

    const float* aBase = xs + (ty * 4) * XSS;
    const ulonglong2* bG = (const ulonglong2*)g_chat2 + tx;  // 16B chunks

    #pragma unroll 1
    for (int pp = 0; pp < 150; pp += 2) {
        // ---- load block: A for both pairs (LDS.128), B for both pairs (LDG.128)
        F4U2 a[4];
        #pragma unroll
        for (int i = 0; i < 4; i++)
            a[i].f = *(const float4*)(aBase + i * XSS + 2 * pp);
        ulonglong2 B00 = __ldg(bG + pp * 32);            // pp,   k=4tx..4tx+1
        ulonglong2 B01 = __ldg(bG + pp * 32 + 16);       // pp,   k=4tx+2..4tx+3
        ulonglong2 B10 = __ldg(bG + pp * 32 + 32);       // pp+1
        ulonglong2 B11 = __ldg(bG + pp * 32 + 48);       // pp+1
        // ---- math block: 32 fma2
        #pragma unroll
        for (int i = 0; i < 4; i++) {
            fma2(acc[i][0], a[i].u[0], B00.x);
            fma2(acc[i][1], a[i].u[0], B00.y);
            fma2(acc[i][2], a[i].u[0], B01.x);
            fma2(acc[i][3], a[i].u[0], B01.y);
        }
        #pragma unroll
        for (int i = 0; i < 4; i++) {
            fma2(acc[i][0], a[i].u[1], B10.x);
            fma2(acc[i][1], a[i].u[1], B10.y);
            fma2(acc[i][2], a[i].u[1], B11.x);
            fma2(acc[i][3], a[i].u[1], B11.y);
        }
    }

    #pragma unroll
    for (int i = 0; i < 4; i++) {
        int row = row0 + ty * 4 + i;
        float iv = inv[ty * 4 + i];
        float* gout = g_G + (size_t)row * KK;
        #pragma unroll
        for (int j = 0; j < 4; j++) {
            int k = tx * 4 + j;
            if (k < KK) gout[k] = sum2(acc[i][j]) * iv;
        }
    }
}

// ============================================================
// K2: per-batch conv(11) + relu + max-over-k + softmax over s.
// One block per b, 512 threads. Padded smem tile, stride 51.
// ============================================================
#define GST 51
#define GROWS (SS + 2*RR)   // 522

__global__ void __launch_bounds__(512, 1)
k2_attn(const float* __restrict__ cw, const float* __restrict__ cbp) {
    extern __shared__ float Gs[];   // GROWS * GST
    __shared__ float red1[16], red2[16];
    __shared__ float wloc[11];
    __shared__ float sc[3];         // [0]=conv_b, [1]=max, [2]=sum

    const int b = blockIdx.x, tid = threadIdx.x;
    if (tid < 11) wloc[tid] = cw[tid];
    if (tid == 16) sc[0] = cbp[0];

    for (int i = tid; i < RR * GST; i += 512) {
        Gs[i] = 0.f;
        Gs[(SS + RR) * GST + i] = 0.f;
    }
    const float* Gb = g_G + (size_t)b * SS * KK;
    for (int i = tid; i < SS * KK; i += 512) {
        int s = i / KK, k = i - s * KK;
        Gs[(s + RR) * GST + k] = Gb[i];
    }
    __syncthreads();

    const int s = tid;
    const float cbv = sc[0];
    float m = 0.f;   // relu >= 0
    for (int k = 0; k < KK; k++) {
        float v = cbv;
        const float* gp = Gs + s * GST + k;
        #pragma unroll
        for (int j = 0; j < 11; j++) v = fmaf(wloc[j], gp[j * GST], v);
        m = fmaxf(m, fmaxf(v, 0.f));
    }

    const int lane = tid & 31, warp = tid >> 5;
    float mx = m;
    #pragma unroll
    for (int o = 16; o; o >>= 1) mx = fmaxf(mx, __shfl_xor_sync(0xffffffffu, mx, o));
    if (lane == 0) red1[warp] = mx;
    __syncthreads();
    if (warp == 0) {
        float v = (lane < 16) ? red1[lane] : -1e30f;
        #pragma unroll
        for (int o = 8; o; o >>= 1) v = fmaxf(v, __shfl_xor_sync(0xffffffffu, v, o));
        if (lane == 0) sc[1] = v;
    }
    __syncthreads();
    float e = expf(m - sc[1]);
    float sum = e;
    #pragma unroll
    for (int o = 16; o; o >>= 1) sum += __shfl_xor_sync(0xffffffffu, sum, o);
    if (lane == 0) red2[warp] = sum;
    __syncthreads();
    if (warp == 0) {
        float v = (lane < 16) ? red2[lane] : 0.f;
        #pragma unroll
        for (int o = 8; o; o >>= 1) v += __shfl_xor_sync(0xffffffffu, v, o);
        if (lane == 0) sc[2] = v;
    }
    __syncthreads();
    g_beta[b * SS + s] = e / sc[2];
}

// ============================================================
// K3a: pooling partials. grid (32 chunks, 64 b), 320 threads.
// 16 s per block, 8-deep MLP.
// ============================================================
__global__ void __launch_bounds__(320, 4)
k3a_pool(const int* __restrict__ idx, const float* __restrict__ emb) {
    __shared__ float sbeta[16];
    __shared__ int   sidx[16];
    const int cx = blockIdx.x, b = blockIdx.y, tid = threadIdx.x;
    const int s0 = b * SS + cx * 16;
    if (tid < 16) {
        sbeta[tid] = g_beta[s0 + tid];
        sidx[tid]  = idx[s0 + tid];
    }
    __syncthreads();
    if (tid < PD) {
        float a[8];
        #pragma unroll
        for (int i = 0; i < 8; i++) a[i] = 0.f;
        #pragma unroll
        for (int s = 0; s < 16; s += 8) {
            #pragma unroll
            for (int i = 0; i < 8; i++)
                a[i] = fmaf(sbeta[s + i],
                            __ldg(emb + (size_t)sidx[s + i] * PD + tid), a[i]);
        }
        float r = ((a[0] + a[1]) + (a[2] + a[3])) + ((a[4] + a[5]) + (a[6] + a[7]));
        g_part[(b * NCH + cx) * PD + tid] = r;
    }
}

// ============================================================
// K3b: combine partials + final GEMV out = pooled @ W2^T + b2.
// ============================================================
__global__ void __launch_bounds__(320, 4)
k3b_out(const float* __restrict__ W2, const float* __restrict__ b2,
        float* __restrict__ out) {
    __shared__ float pooled[PD];
    const int b = blockIdx.x, tid = threadIdx.x;
    if (tid < PD) {
        float s = 0.f;
        #pragma unroll
        for (int c = 0; c < NCH; c++) s += g_part[(b * NCH + c) * PD + tid];
        pooled[tid] = s * (1.0f / (float)SS);
    }
    __syncthreads();

    const int warp = tid >> 5, lane = tid & 31;  // 10 warps x 5 k
    #pragma unroll
    for (int kk = 0; kk < 5; kk++) {
        int k = warp * 5 + kk;
        float d = 0.f;
        for (int p = lane; p < PD; p += 32) d = fmaf(pooled[p], W2[k * PD + p], d);
        #pragma unroll
        for (int o = 16; o; o >>= 1) d += __shfl_xor_sync(0xffffffffu, d, o);
        if (lane == 0) out[b * KK + k] = d + b2[k];
    }
}

// ============================================================
extern "C" void kernel_launch(void* const* d_in, const int* in_sizes, int n_in,
                              void* d_out, int out_size) {
    const int*   idx    = (const int*)d_in[0];
    const float* emb    = (const float*)d_in[1];
    const float* C      = (const float*)d_in[2];
    const float* conv_w = (const float*)d_in[3];
    const float* conv_b = (const float*)d_in[4];
    const float* W2     = (const float*)d_in[5];
    const float* b2     = (const float*)d_in[6];
    float*       out    = (float*)d_out;

    const int sm1 = BM * XSS * (int)sizeof(float);              // ~39 KB (5 blocks/SM)
    const int sm2 = GROWS * GST * (int)sizeof(float);           // ~106 KB
    cudaFuncSetAttribute(k1_scores, cudaFuncAttributeMaxDynamicSharedMemorySize, sm1);
    cudaFuncSetAttribute(k2_attn,   cudaFuncAttributeMaxDynamicSharedMemorySize, sm2);

    k0_chat<<<4, 256>>>(C);
    k1_scores<<<NROWS / BM, 128, sm1>>>(idx, emb);
    k2_attn<<<BB, 512, sm2>>>(conv_w, conv_b);
    k3a_pool<<<dim3(NCH, BB), 320>>>(idx, emb);
    k3b_out<<<BB, 320>>>(W2, b2, out);
}